// round 8
// baseline (speedup 1.0000x reference)
#include <cuda_runtime.h>
#include <cuda_bf16.h>
#include <math.h>

#define BATCH 8
#define SEQ   8192
#define DIM   512
#define HEADS 8
#define DH    64
#define SL    32
#define MTOT  (BATCH * SEQ)
#define NSPLIT 128                 // 64 tokens per split
#define QDIM  (HEADS * SL)         // 256

// ---------------- device scratch ----------------
__device__ float g_xmid[(size_t)MTOT * DIM];
__device__ float g_q   [(size_t)MTOT * QDIM];
__device__ float g_S1p [(size_t)NSPLIT * 64 * SL * DH];
__device__ float g_S0p [(size_t)NSPLIT * 64 * SL];
__device__ float g_kv  [(size_t)64 * SL * DH];
__device__ float g_Z   [(size_t)BATCH * QDIM * DIM];

__device__ __forceinline__ unsigned f2tf32(float f) {
    unsigned u;
    asm("cvt.rna.tf32.f32 %0, %1;" : "=r"(u) : "f"(f));
    return u;
}
__device__ __forceinline__ float tf32r(float f) { return __uint_as_float(f2tf32(f)); }
__device__ __forceinline__ float4 tf32r4(float4 v) {
    float4 o; o.x = tf32r(v.x); o.y = tf32r(v.y); o.z = tf32r(v.z); o.w = tf32r(v.w);
    return o;
}
__device__ __forceinline__ void mma_tf32(float* c, const unsigned* a, const unsigned* b) {
    asm volatile(
        "mma.sync.aligned.m16n8k8.row.col.f32.tf32.tf32.f32 "
        "{%0,%1,%2,%3}, {%4,%5,%6,%7}, {%8,%9}, {%0,%1,%2,%3};"
        : "+f"(c[0]), "+f"(c[1]), "+f"(c[2]), "+f"(c[3])
        : "r"(a[0]), "r"(a[1]), "r"(a[2]), "r"(a[3]), "r"(b[0]), "r"(b[1]));
}
__device__ __forceinline__ unsigned smem_u32(const void* p) {
    return (unsigned)__cvta_generic_to_shared(p);
}
#define CP16(dst, src) asm volatile("cp.async.cg.shared.global [%0], [%1], 16;" :: "r"(dst), "l"(src))
#define CP_COMMIT()    asm volatile("cp.async.commit_group;")
#define CP_WAIT1()     asm volatile("cp.async.wait_group 1;")
#define CP_WAIT0()     asm volatile("cp.async.wait_group 0;")

// ---------------- TF32 GEMM, 128x128 tile, BK=16, cp.async 2-stage, batched (round-6 proven) ----
__global__ __launch_bounds__(256) void tf32gemm_bias_kernel(
    const float* __restrict__ A, const float* __restrict__ W,
    const float* __restrict__ bias, float* __restrict__ C, int K,
    size_t zStrideA, size_t zStrideW, size_t zStrideC)
{
    const int N = 512;
    __shared__ float As[2][128][20];
    __shared__ float Bs[2][16][136];

    const int tid  = threadIdx.x;
    const int warp = tid >> 5;
    const int lane = tid & 31;
    const int g = lane >> 2;
    const int t = lane & 3;

    const int rowBase = blockIdx.y * 128;
    const int colBase = blockIdx.x * 128;
    const int wm = (warp & 3) * 32;
    const int wn = (warp >> 2) * 64;

    A += zStrideA * blockIdx.z;
    W += zStrideW * blockIdx.z;
    C += zStrideC * blockIdx.z;

    float acc[2][8][4];
#pragma unroll
    for (int mt = 0; mt < 2; mt++)
#pragma unroll
        for (int nt = 0; nt < 8; nt++)
#pragma unroll
            for (int i = 0; i < 4; i++) acc[mt][nt][i] = 0.f;

    const int aRow = tid >> 2;
    const int aC4  = (tid & 3) * 4;
    const int bRow = tid >> 5;
    const int bC4  = (tid & 31) * 4;

    const float* Ag  = A + (size_t)(rowBase + aRow) * K + aC4;
    const float* Ag2 = Ag + (size_t)64 * K;
    const float* Bg  = W + (size_t)bRow * N + colBase + bC4;
    const float* Bg2 = Bg + (size_t)8 * N;

    unsigned sA0 = smem_u32(&As[0][aRow][aC4]);
    unsigned sA1 = smem_u32(&As[0][aRow + 64][aC4]);
    unsigned sB0 = smem_u32(&Bs[0][bRow][bC4]);
    unsigned sB1 = smem_u32(&Bs[0][bRow + 8][bC4]);
    const unsigned strideA = 128 * 20 * 4;
    const unsigned strideB = 16 * 136 * 4;

    CP16(sA0, Ag);  CP16(sA1, Ag2);
    CP16(sB0, Bg);  CP16(sB1, Bg2);
    CP_COMMIT();

    const int nIter = K >> 4;
#pragma unroll 1
    for (int it = 0; it < nIter; it++) {
        const int kt = it * 16;
        const int cur = it & 1;
        if (it + 1 < nIter) {
            const unsigned off  = (cur ^ 1) ? strideA : 0;
            const unsigned offB = (cur ^ 1) ? strideB : 0;
            CP16(sA0 + off, Ag + kt + 16);
            CP16(sA1 + off, Ag2 + kt + 16);
            CP16(sB0 + offB, Bg + (size_t)(kt + 16) * N);
            CP16(sB1 + offB, Bg2 + (size_t)(kt + 16) * N);
            CP_COMMIT();
            CP_WAIT1();
        } else {
            CP_WAIT0();
        }
        __syncthreads();

#pragma unroll
        for (int ks = 0; ks < 16; ks += 8) {
            unsigned af[2][4], bf[8][2];
#pragma unroll
            for (int mt = 0; mt < 2; mt++) {
                const int r0 = wm + mt * 16 + g;
                af[mt][0] = f2tf32(As[cur][r0    ][ks + t    ]);
                af[mt][1] = f2tf32(As[cur][r0 + 8][ks + t    ]);
                af[mt][2] = f2tf32(As[cur][r0    ][ks + t + 4]);
                af[mt][3] = f2tf32(As[cur][r0 + 8][ks + t + 4]);
            }
#pragma unroll
            for (int nt = 0; nt < 8; nt++) {
                const int c0 = wn + nt * 8 + g;
                bf[nt][0] = f2tf32(Bs[cur][ks + t    ][c0]);
                bf[nt][1] = f2tf32(Bs[cur][ks + t + 4][c0]);
            }
#pragma unroll
            for (int mt = 0; mt < 2; mt++)
#pragma unroll
                for (int nt = 0; nt < 8; nt++)
                    mma_tf32(acc[mt][nt], af[mt], bf[nt]);
        }
        __syncthreads();
    }

#pragma unroll
    for (int nt = 0; nt < 8; nt++) {
        const int col = colBase + wn + nt * 8 + 2 * t;
        const float bx = bias[col], by = bias[col + 1];
#pragma unroll
        for (int mt = 0; mt < 2; mt++) {
            const int row0 = rowBase + wm + mt * 16 + g;
            float2 o0, o1;
            o0.x = acc[mt][nt][0] + bx; o0.y = acc[mt][nt][1] + by;
            o1.x = acc[mt][nt][2] + bx; o1.y = acc[mt][nt][3] + by;
            *reinterpret_cast<float2*>(&C[(size_t)row0 * N + col])       = o0;
            *reinterpret_cast<float2*>(&C[(size_t)(row0 + 8) * N + col]) = o1;
        }
    }
}

// ---------------- Fused kv + q kernel: one 64-token chunk per CTA, smem union ----------------
// grid (NSPLIT, HEADS, BATCH), 128 threads (4 warps).
// P = X(64x64) @ [Wq|Wk|Wv](64x128) via mma; warp0->Q(softmax->g_q), warp1->exp(K)->Es^T,
// warps2,3->V->Vs. Then S1 = Es @ Vs (mma), S0 = col sums of Es -> per-split partials.
// SMEM: Xs [64][68] | union{ Ws [64][136]  -->  Es[32][68] + Vs[64][72] + Qs[64][36] }
#define KVQ_SMEM ((64*68 + 32*68 + 64*72 + 64*36) * 4)   // 53760 bytes

__global__ __launch_bounds__(128) void kvq_fused_kernel(
    const float* __restrict__ xmid, const float* __restrict__ Wq,
    const float* __restrict__ Wk, const float* __restrict__ Wv)
{
    extern __shared__ float sm[];
    float* Xs = sm;                  // [64][68]
    float* Ws = sm + 64 * 68;        // [64][136] (transient)
    float* Es = sm + 64 * 68;        // [32][68]  (aliases Ws after fragment build)
    float* Vs = Es + 32 * 68;        // [64][72]
    float* Qs = Vs + 64 * 72;        // [64][36]

    const int split = blockIdx.x;
    const int h = blockIdx.y;
    const int b = blockIdx.z;
    const int bh = b * HEADS + h;
    const int tid = threadIdx.x;
    const int w = tid >> 5;
    const int lane = tid & 31;
    const int g = lane >> 2;
    const int t = lane & 3;
    const int n0 = split * 64;

    // loads: weights (transient) + X tile
    for (int idx = tid; idx < 64 * 32; idx += 128) Ws[(idx >> 5) * 136 + (idx & 31)]        = tf32r(Wq[idx]);
    for (int idx = tid; idx < 64 * 32; idx += 128) Ws[(idx >> 5) * 136 + 32 + (idx & 31)]   = tf32r(Wk[idx]);
    for (int idx = tid; idx < 64 * 64; idx += 128) Ws[(idx >> 6) * 136 + 64 + (idx & 63)]   = tf32r(Wv[idx]);
    for (int idx = tid; idx < 64 * 16; idx += 128) {
        int r = idx >> 4, c4 = (idx & 15) * 4;
        float4 v = *reinterpret_cast<const float4*>(
            &xmid[(size_t)(b * SEQ + n0 + r) * DIM + h * DH + c4]);
        *reinterpret_cast<float4*>(&Xs[r * 68 + c4]) = tf32r4(v);
    }
    __syncthreads();

    // weight B-fragments: warp w owns cols [32w, 32w+32) -> 4 nt tiles
    unsigned bfw[4][8][2];
#pragma unroll
    for (int nt = 0; nt < 4; nt++)
#pragma unroll
        for (int ks = 0; ks < 8; ks++) {
            const int c0 = 32 * w + nt * 8 + g;
            bfw[nt][ks][0] = __float_as_uint(Ws[(8 * ks + t)     * 136 + c0]);
            bfw[nt][ks][1] = __float_as_uint(Ws[(8 * ks + t + 4) * 136 + c0]);
        }

    // projection mma: 64 rows (4 mt) x warp's 32 cols (4 nt), k=64
    float pacc[4][4][4];
#pragma unroll
    for (int mt = 0; mt < 4; mt++)
#pragma unroll
        for (int nt = 0; nt < 4; nt++)
#pragma unroll
            for (int i = 0; i < 4; i++) pacc[mt][nt][i] = 0.f;

#pragma unroll
    for (int ks = 0; ks < 8; ks++) {
        unsigned af[4][4];
#pragma unroll
        for (int mt = 0; mt < 4; mt++) {
            const int r0 = mt * 16 + g;
            af[mt][0] = __float_as_uint(Xs[(r0    ) * 68 + 8 * ks + t    ]);
            af[mt][1] = __float_as_uint(Xs[(r0 + 8) * 68 + 8 * ks + t    ]);
            af[mt][2] = __float_as_uint(Xs[(r0    ) * 68 + 8 * ks + t + 4]);
            af[mt][3] = __float_as_uint(Xs[(r0 + 8) * 68 + 8 * ks + t + 4]);
        }
#pragma unroll
        for (int mt = 0; mt < 4; mt++)
#pragma unroll
            for (int nt = 0; nt < 4; nt++)
                mma_tf32(pacc[mt][nt], af[mt], bfw[nt][ks]);
    }
    __syncthreads();   // all Ws reads complete -> union region reusable

    // epilogue by warp role (writes into union region)
#pragma unroll
    for (int mt = 0; mt < 4; mt++)
#pragma unroll
        for (int nt = 0; nt < 4; nt++) {
            const int c0 = 32 * w + nt * 8 + 2 * t;
            const int r0 = mt * 16 + g;
            float v0 = pacc[mt][nt][0], v1 = pacc[mt][nt][1];
            float v2 = pacc[mt][nt][2], v3 = pacc[mt][nt][3];
            if (w == 0) {                       // Q raw
                Qs[(r0    ) * 36 + c0]     = v0;
                Qs[(r0    ) * 36 + c0 + 1] = v1;
                Qs[(r0 + 8) * 36 + c0]     = v2;
                Qs[(r0 + 8) * 36 + c0 + 1] = v3;
            } else if (w == 1) {                // E = exp(K), transposed [slice][token]
                const int s = c0 - 32;
                Es[(s    ) * 68 + r0]     = tf32r(expf(v0));
                Es[(s + 1) * 68 + r0]     = tf32r(expf(v1));
                Es[(s    ) * 68 + r0 + 8] = tf32r(expf(v2));
                Es[(s + 1) * 68 + r0 + 8] = tf32r(expf(v3));
            } else {                            // V [token][channel]
                const int c = c0 - 64;
                Vs[(r0    ) * 72 + c]     = tf32r(v0);
                Vs[(r0    ) * 72 + c + 1] = tf32r(v1);
                Vs[(r0 + 8) * 72 + c]     = tf32r(v2);
                Vs[(r0 + 8) * 72 + c + 1] = tf32r(v3);
            }
        }
    __syncthreads();

    // softmax over slice dim (one token per thread)
    float s0val = 0.f;
    if (tid < 64) {
        float m = Qs[tid * 36 + 0];
#pragma unroll
        for (int s = 1; s < 32; s++) m = fmaxf(m, Qs[tid * 36 + s]);
        float e[32], sum = 0.f;
#pragma unroll
        for (int s = 0; s < 32; s++) { e[s] = expf(Qs[tid * 36 + s] - m); sum += e[s]; }
        float inv = 1.f / sum;
#pragma unroll
        for (int s = 0; s < 32; s++) Qs[tid * 36 + s] = e[s] * inv;
    } else if (tid < 96) {
        // S0: column sums of E
        const int s = tid - 64;
#pragma unroll
        for (int r = 0; r < 64; r++) s0val += Es[s * 68 + r];
    }
    __syncthreads();

    // coalesced store of softmaxed Q
    for (int idx = tid; idx < 64 * 8; idx += 128) {
        int r = idx >> 3, c4 = (idx & 7) * 4;
        float4 v = *reinterpret_cast<const float4*>(&Qs[r * 36 + c4]);
        *reinterpret_cast<float4*>(
            &g_q[(size_t)(b * SEQ + n0 + r) * QDIM + h * SL + c4]) = v;
    }

    // S1 = Es(32x64tok) @ Vs(64tok x 64); warp w: cols [16w, 16w+16)
    float accS1[2][2][4];
#pragma unroll
    for (int mt = 0; mt < 2; mt++)
#pragma unroll
        for (int nt = 0; nt < 2; nt++)
#pragma unroll
            for (int i = 0; i < 4; i++) accS1[mt][nt][i] = 0.f;

#pragma unroll
    for (int ks = 0; ks < 8; ks++) {
        unsigned af2[2][4];
#pragma unroll
        for (int mt = 0; mt < 2; mt++) {
            const int r0 = mt * 16 + g;
            af2[mt][0] = __float_as_uint(Es[(r0    ) * 68 + 8 * ks + t    ]);
            af2[mt][1] = __float_as_uint(Es[(r0 + 8) * 68 + 8 * ks + t    ]);
            af2[mt][2] = __float_as_uint(Es[(r0    ) * 68 + 8 * ks + t + 4]);
            af2[mt][3] = __float_as_uint(Es[(r0 + 8) * 68 + 8 * ks + t + 4]);
        }
#pragma unroll
        for (int nt = 0; nt < 2; nt++) {
            const int c0 = 16 * w + nt * 8 + g;
            unsigned bf2[2];
            bf2[0] = __float_as_uint(Vs[(8 * ks + t    ) * 72 + c0]);
            bf2[1] = __float_as_uint(Vs[(8 * ks + t + 4) * 72 + c0]);
#pragma unroll
            for (int mt = 0; mt < 2; mt++)
                mma_tf32(accS1[mt][nt], af2[mt], bf2);
        }
    }

    // write per-split partials
    float* base = g_S1p + ((size_t)split * 64 + bh) * (SL * DH);
#pragma unroll
    for (int mt = 0; mt < 2; mt++)
#pragma unroll
        for (int nt = 0; nt < 2; nt++) {
            const int s0 = mt * 16 + g;
            const int c  = 16 * w + nt * 8 + 2 * t;
            base[(s0    ) * DH + c]     = accS1[mt][nt][0];
            base[(s0    ) * DH + c + 1] = accS1[mt][nt][1];
            base[(s0 + 8) * DH + c]     = accS1[mt][nt][2];
            base[(s0 + 8) * DH + c + 1] = accS1[mt][nt][3];
        }
    if (tid >= 64 && tid < 96)
        g_S0p[((size_t)split * 64 + bh) * SL + (tid - 64)] = s0val;
}

// ---------------- kv finalize ----------------
__global__ __launch_bounds__(256) void kv_final_kernel()
{
    int idx = blockIdx.x * 256 + threadIdx.x;
    if (idx >= 64 * SL * DH) return;
    int bh = idx >> 11;
    int sc = idx & 2047;
    int s  = sc >> 6;
    float s1 = 0.f, s0 = 0.f;
    for (int sp = 0; sp < NSPLIT; sp++) {
        s1 += g_S1p[((size_t)sp * 64 + bh) * (SL * DH) + sc];
        s0 += g_S0p[((size_t)sp * 64 + bh) * SL + s];
    }
    g_kv[idx] = s1 / s0;
}

// ---------------- Z prep: Z[b][h*32+s][:] = kv[b,h] @ W_out[h*64:(h+1)*64, :] ----------------
__global__ __launch_bounds__(256) void zprep_kernel(const float* __restrict__ W_out)
{
    const int cb = blockIdx.x;
    const int h  = blockIdx.y;
    const int b  = blockIdx.z;
    const int bh = b * HEADS + h;
    const int tid = threadIdx.x;

    __shared__ float kvs[32][64];
    __shared__ float Wos[64][64];

    for (int idx = tid; idx < SL * DH; idx += 256)
        kvs[idx >> 6][idx & 63] = g_kv[(size_t)bh * (SL * DH) + idx];
    for (int idx = tid; idx < 64 * 64; idx += 256) {
        int r = idx >> 6, c = idx & 63;
        Wos[r][c] = W_out[(size_t)(h * DH + r) * DIM + cb * 64 + c];
    }
    __syncthreads();

    for (int idx = tid; idx < SL * 64; idx += 256) {
        int s = idx >> 6, c = idx & 63;
        float d = 0.f;
#pragma unroll
        for (int k = 0; k < 64; k++) d = fmaf(kvs[s][k], Wos[k][c], d);
        g_Z[((size_t)b * QDIM + h * SL + s) * DIM + cb * 64 + c] = d;
    }
}

// ---------------- launch ----------------
extern "C" void kernel_launch(void* const* d_in, const int* in_sizes, int n_in,
                              void* d_out, int out_size)
{
    const float* x     = (const float*)d_in[0];
    const float* W_in  = (const float*)d_in[1];
    const float* b_in  = (const float*)d_in[2];
    const float* Wq    = (const float*)d_in[3];
    const float* Wk    = (const float*)d_in[4];
    const float* Wv    = (const float*)d_in[5];
    const float* W_out = (const float*)d_in[6];
    const float* b_out = (const float*)d_in[7];
    float* out = (float*)d_out;

    float *xmid, *q, *Z;
    cudaGetSymbolAddress((void**)&xmid, g_xmid);
    cudaGetSymbolAddress((void**)&q, g_q);
    cudaGetSymbolAddress((void**)&Z, g_Z);

    cudaFuncSetAttribute(kvq_fused_kernel,
                         cudaFuncAttributeMaxDynamicSharedMemorySize, KVQ_SMEM);

    // 1) x_mid = x @ W_in + b_in   (K=512)
    dim3 g1(DIM / 128, MTOT / 128, 1);
    tf32gemm_bias_kernel<<<g1, 256>>>(x, W_in, b_in, xmid, DIM, 0, 0, 0);

    // 2) fused: q-softmax -> g_q, kv split partials (64 tokens per CTA)
    dim3 kvGrid(NSPLIT, HEADS, BATCH);
    kvq_fused_kernel<<<kvGrid, 128, KVQ_SMEM>>>(xmid, Wq, Wk, Wv);

    // 3) kv finalize
    kv_final_kernel<<<(64 * SL * DH + 255) / 256, 256>>>();

    // 4) Z = kv @ W_out
    dim3 zGrid(DIM / 64, HEADS, BATCH);
    zprep_kernel<<<zGrid, 256>>>(W_out);

    // 5) out = Q @ Z_b + b_out    (K=256, batched over z)
    dim3 g2(DIM / 128, SEQ / 128, BATCH);
    tf32gemm_bias_kernel<<<g2, 256>>>(q, Z, b_out, out, QDIM,
                                      (size_t)SEQ * QDIM,
                                      (size_t)QDIM * DIM,
                                      (size_t)SEQ * DIM);
}